// round 1
// baseline (speedup 1.0000x reference)
#include <cuda_runtime.h>

// Global double accumulator scratch (8 output values).
__device__ double g_acc[8];

__global__ void zero_acc_kernel() {
    if (threadIdx.x < 8) g_acc[threadIdx.x] = 0.0;
}

__global__ __launch_bounds__(256) void integrate_kernel(
    const float* __restrict__ nodal_values,  // (N_NODES, 8)
    const float* __restrict__ coords,        // (N_NODES, 2)
    const int*   __restrict__ elements,      // (E, 3)
    int n_elements)
{
    float acc[8];
#pragma unroll
    for (int v = 0; v < 8; v++) acc[v] = 0.0f;

    const int stride = gridDim.x * blockDim.x;
    for (int e = blockIdx.x * blockDim.x + threadIdx.x; e < n_elements; e += stride) {
        const int i0 = elements[3 * e + 0];
        const int i1 = elements[3 * e + 1];
        const int i2 = elements[3 * e + 2];

        const float2 c0 = *reinterpret_cast<const float2*>(coords + 2 * i0);
        const float2 c1 = *reinterpret_cast<const float2*>(coords + 2 * i1);
        const float2 c2 = *reinterpret_cast<const float2*>(coords + 2 * i2);

        // J = [[x1-x0, y1-y0],[x2-x0, y2-y0]] for Tri3; det is constant per element.
        const float det = (c1.x - c0.x) * (c2.y - c0.y) - (c1.y - c0.y) * (c2.x - c0.x);
        // sum_q w[q] * N_q[q][n] == 1/6 for every node n  (3-pt symmetric rule)
        const float s = det * (1.0f / 6.0f);

        const float4 a0 = *reinterpret_cast<const float4*>(nodal_values + 8 * i0);
        const float4 b0 = *reinterpret_cast<const float4*>(nodal_values + 8 * i0 + 4);
        const float4 a1 = *reinterpret_cast<const float4*>(nodal_values + 8 * i1);
        const float4 b1 = *reinterpret_cast<const float4*>(nodal_values + 8 * i1 + 4);
        const float4 a2 = *reinterpret_cast<const float4*>(nodal_values + 8 * i2);
        const float4 b2 = *reinterpret_cast<const float4*>(nodal_values + 8 * i2 + 4);

        acc[0] += s * (a0.x + a1.x + a2.x);
        acc[1] += s * (a0.y + a1.y + a2.y);
        acc[2] += s * (a0.z + a1.z + a2.z);
        acc[3] += s * (a0.w + a1.w + a2.w);
        acc[4] += s * (b0.x + b1.x + b2.x);
        acc[5] += s * (b0.y + b1.y + b2.y);
        acc[6] += s * (b0.z + b1.z + b2.z);
        acc[7] += s * (b0.w + b1.w + b2.w);
    }

    // Warp reduction for each of 8 accumulators.
#pragma unroll
    for (int v = 0; v < 8; v++) {
#pragma unroll
        for (int off = 16; off > 0; off >>= 1)
            acc[v] += __shfl_down_sync(0xFFFFFFFFu, acc[v], off);
    }

    __shared__ float sred[8][8];  // [warp][value]
    const int warp = threadIdx.x >> 5;
    const int lane = threadIdx.x & 31;
    if (lane == 0) {
#pragma unroll
        for (int v = 0; v < 8; v++) sred[warp][v] = acc[v];
    }
    __syncthreads();

    if (threadIdx.x < 8) {
        float sum = 0.0f;
        const int nwarps = blockDim.x >> 5;
#pragma unroll
        for (int w = 0; w < 8; w++)
            if (w < nwarps) sum += sred[w][threadIdx.x];
        atomicAdd(&g_acc[threadIdx.x], (double)sum);
    }
}

__global__ void finalize_kernel(float* __restrict__ out) {
    if (threadIdx.x < 8) out[threadIdx.x] = (float)g_acc[threadIdx.x];
}

extern "C" void kernel_launch(void* const* d_in, const int* in_sizes, int n_in,
                              void* d_out, int out_size) {
    const float* nodal_values = (const float*)d_in[0];
    const float* coords       = (const float*)d_in[1];
    const int*   elements     = (const int*)d_in[2];
    float* out = (float*)d_out;

    const int n_elements = in_sizes[2] / 3;

    zero_acc_kernel<<<1, 32>>>();
    const int threads = 256;
    const int blocks = 1024;
    integrate_kernel<<<blocks, threads>>>(nodal_values, coords, elements, n_elements);
    finalize_kernel<<<1, 32>>>(out);
}